// round 16
// baseline (speedup 1.0000x reference)
#include <cuda_runtime.h>
#include <cuda_fp16.h>

#define NODES   6272
#define CIN     8
#define COUT    16
#define CAPS    10
#define BATCH   64
#define PAIRS   (BATCH * CAPS)          // 640
#define CHUNK   64
#define NCHUNK  (NODES / CHUNK)         // 98
#define K1_THREADS 256
#define NSLICE  7
#define SLICE   (NODES / NSLICE)        // 896 nodes = 1792 uint4 half-rows
#define P_THREADS 224                   // 7 warps
#define P_WARPS 7
#define P_ITERS 4                       // 2 half-rows per thread per iter

// ---------------- device scratch ----------
__device__ __half g_uh[(size_t)PAIRS * NODES * COUT];          // 128.4 MB
__device__ float  g_p0[(size_t)PAIRS * NCHUNK * COUT];
__device__ float  g_ps1[(size_t)PAIRS * NSLICE * (COUT + 1)];
__device__ float  g_ps2[(size_t)PAIRS * NSLICE * (COUT + 1)];
__device__ int    g_ctr[PAIRS];         // fan-in counters (self-resetting)

// ---------------- packed helpers -------------------------------------------
__device__ __forceinline__ unsigned long long pk2(float lo, float hi) {
    unsigned long long r;
    asm("mov.b64 %0, {%1, %2};" : "=l"(r) : "f"(lo), "f"(hi));
    return r;
}
__device__ __forceinline__ void upk2(unsigned long long v, float& lo, float& hi) {
    asm("mov.b64 {%0, %1}, %2;" : "=f"(lo), "=f"(hi) : "l"(v));
}
__device__ __forceinline__ unsigned long long fma2(unsigned long long a,
                                                   unsigned long long b,
                                                   unsigned long long c) {
    unsigned long long d;
    asm("fma.rn.f32x2 %0, %1, %2, %3;" : "=l"(d) : "l"(a), "l"(b), "l"(c));
    return d;
}
__device__ __forceinline__ unsigned hadd2u(unsigned a, unsigned b) {
    __half2 r = __hadd2(*reinterpret_cast<__half2*>(&a),
                        *reinterpret_cast<__half2*>(&b));
    return *reinterpret_cast<unsigned*>(&r);
}

// FMA-pipe exp (no MUFU). rel err ~2.4e-6, clamped to +-70.
__device__ __forceinline__ float fexp(float a) {
    a = fminf(fmaxf(a, -70.f), 70.f);
    float zm = fmaf(a, 1.442695041f, 12582912.0f);
    int   n  = __float_as_int(zm);
    float fj = zm - 12582912.0f;
    float f  = fmaf(a, 1.442695041f, -fj);
    float p  = 0.0013333558f;
    p = fmaf(p, f, 0.0096181291f);
    p = fmaf(p, f, 0.055504109f);
    p = fmaf(p, f, 0.24022651f);
    p = fmaf(p, f, 0.69314718f);
    p = fmaf(p, f, 1.0f);
    return p * __int_as_float((n + (127 - 0x4B400000)) << 23);
}

// ---------------------------------------------------------------------------
// K1: u_hat -> fp16 + pass-0 partials. fp16x2 pair-reduce (R15) + this round:
// strength-reduced pointers (g_uh/xs/p0 advanced by constant strides, no per-bi
// 64-bit rederivation) and slot-major psum[bi][4][32] so the tail uses LDS.128.
// ---------------------------------------------------------------------------
__global__ void __launch_bounds__(K1_THREADS, 4)
uhat_kernel(const float* __restrict__ x, const float* __restrict__ W) {
    __shared__ __align__(16) char smbuf[32768];   // union: Ws | xs+psum
    float* Ws = reinterpret_cast<float*>(smbuf);                 // [8192]
    float* xs = reinterpret_cast<float*>(smbuf);                 // [4096]
    uint2 (*psum)[4][32] =
        reinterpret_cast<uint2(*)[4][32]>(smbuf + 16384);        // [8][4][32]

    const int c  = blockIdx.y;
    const int n0 = blockIdx.x * CHUNK;
    const int t    = threadIdx.x;
    const int lane = t & 31;
    const int warp = t >> 5;
    const int n = t >> 2;
    const int q = t & 3;

    const float4* Wg = reinterpret_cast<const float4*>(
        W + ((size_t)c * NODES + n0) * (CIN * COUT));
    float4* Ws4 = reinterpret_cast<float4*>(Ws);
    #pragma unroll
    for (int i = t; i < CHUNK * CIN * COUT / 4; i += K1_THREADS)
        Ws4[i] = Wg[i];
    __syncthreads();

    unsigned long long Wr2[CIN][2];
    #pragma unroll
    for (int i = 0; i < CIN; i++) {
        const float* wp = Ws + n * (CIN * COUT) + i * COUT + q * 4;
        Wr2[i][0] = pk2(wp[0], wp[1]);
        Wr2[i][1] = pk2(wp[2], wp[3]);
    }

    // strength-reduced hot pointers
    uint2* uhp = reinterpret_cast<uint2*>(
        g_uh + ((size_t)c * NODES + (n0 + n)) * COUT + q * 4);
    const size_t UH_BSTRIDE = (size_t)CAPS * NODES * COUT / 4;   // uint2/batch
    float* p0p = g_p0 + ((size_t)c * NCHUNK + blockIdx.x) * COUT;
    const size_t P0_BSTRIDE = (size_t)CAPS * NCHUNK * COUT;
    // psum slot pointer (fixed per thread; bi via small offset)
    uint2* pslot = ((lane & 4) == 0)
        ? &psum[0][lane & 3][warp * 4 + (lane >> 3)] : nullptr;
    // tail pointer
    uint4* tp = nullptr;
    if (t < 128) tp = reinterpret_cast<uint4*>(&psum[t >> 4][0][0]);

    for (int bg = 0; bg < 8; bg++) {
        __syncthreads();   // protects Ws->xs reuse and psum tail reads
        #pragma unroll
        for (int k = 0; k < 4; k++) {
            int f  = t + k * K1_THREADS;
            int bi = f >> 7, r = f & 127;
            reinterpret_cast<float4*>(xs)[bi * 128 + r] =
                reinterpret_cast<const float4*>(
                    x + ((size_t)(bg * 8 + bi) * NODES + n0) * CIN)[r];
        }
        __syncthreads();

        const float4* xrow = reinterpret_cast<const float4*>(xs + n * CIN);

        #pragma unroll 2
        for (int bi = 0; bi < 8; bi++) {
            float4 xa = xrow[0];
            float4 xb = xrow[1];
            xrow += CHUNK * CIN / 4;   // advance one staged batch
            float xv[CIN] = {xa.x, xa.y, xa.z, xa.w, xb.x, xb.y, xb.z, xb.w};

            unsigned long long o20 = 0ull, o21 = 0ull;
            #pragma unroll
            for (int i = 0; i < CIN; i++) {
                unsigned long long x2 = pk2(xv[i], xv[i]);
                o20 = fma2(x2, Wr2[i][0], o20);
                o21 = fma2(x2, Wr2[i][1], o21);
            }
            float o0, o1, o2, o3;
            upk2(o20, o0, o1);
            upk2(o21, o2, o3);

            __half2 h0 = __floats2half2_rn(o0, o1);
            __half2 h1 = __floats2half2_rn(o2, o3);
            unsigned u0 = *reinterpret_cast<unsigned*>(&h0);
            unsigned u1 = *reinterpret_cast<unsigned*>(&h1);
            *uhp = make_uint2(u0, u1);
            uhp += UH_BSTRIDE;         // next batch, constant stride

            // fp16x2 node-pair reduce (node bit0 = lane bit2): 2 SHFL + HADD2
            unsigned s0 = hadd2u(u0, __shfl_xor_sync(0xffffffffu, u0, 4));
            unsigned s1 = hadd2u(u1, __shfl_xor_sync(0xffffffffu, u1, 4));
            if (pslot) pslot[bi * 128] = make_uint2(s0, s1);   // [bi][4][32]
            // NO barrier — each warp owns its psum slots.
        }
        __syncthreads();

        if (t < 128) {
            const int o = t & 15;
            const int qq = o >> 2, j = o & 3;
            // slot-major: psum[bi][qq][0..31] contiguous -> 16x LDS.128
            const uint4* row = tp + qq * 16;   // 32 uint2 = 16 uint4
            float s = 0.f;
            #pragma unroll
            for (int w = 0; w < 16; w++) {
                uint4 v = row[w];
                unsigned ha = (j < 2) ? v.x : v.y;
                unsigned hb = (j < 2) ? v.z : v.w;
                float2 fa = __half22float2(*reinterpret_cast<__half2*>(&ha));
                float2 fb = __half22float2(*reinterpret_cast<__half2*>(&hb));
                s += ((j & 1) ? fa.y : fa.x) + ((j & 1) ? fb.y : fb.x);
            }
            p0p[(size_t)(t >> 4) * P0_BSTRIDE + o] = s;
        }
        if (t < 128) p0p += 8 * P0_BSTRIDE;   // advance 8 batches per bg
    }
}

// ---------------------------------------------------------------------------
// Pass kernel (exact R15/R10-measured body): half-row lane-paired, 2 rows/
// thread/iter, depth-1 prefetch. mode 0 DESCENDING, mode 1 ASCENDING (L2
// choreography). Prologue computes v0 from g_p0 in-CTA; mode 1 folds
// squash(reduce g_ps1); LAST CTA per pair does final reduce+squash+output.
// ---------------------------------------------------------------------------
__global__ void __launch_bounds__(P_THREADS, 5)
pass_kernel(int mode, float* __restrict__ out) {
    __shared__ float vsm[COUT];
    __shared__ float red[P_WARPS][COUT + 1];
    __shared__ int   is_last;

    const int slice = (mode == 0) ? (NSLICE - 1 - (int)blockIdx.x) : (int)blockIdx.x;
    const int pair  = (mode == 0) ? (PAIRS  - 1 - (int)blockIdx.y) : (int)blockIdx.y;
    const int tid   = threadIdx.x;
    const int lane  = tid & 31;
    const int warp  = tid >> 5;
    const int par   = lane & 1;

    const uint4* __restrict__ base =
        reinterpret_cast<const uint4*>(g_uh) +
        (size_t)pair * (NODES * 2) + slice * (SLICE * 2);

    uint4 cur0 = base[tid];
    uint4 cur1 = base[tid + P_THREADS];

    float p0part = 0.f;
    if (lane < COUT) {
        const float* p = g_p0 + (size_t)pair * NCHUNK * COUT + lane;
        #pragma unroll
        for (int k = 0; k < NCHUNK / P_WARPS; k++)
            p0part += p[(warp + k * P_WARPS) * COUT];
        red[warp][lane] = p0part;
    }
    __syncthreads();

    if (warp == 0) {
        float s = 0.f;
        if (lane < COUT) {
            #pragma unroll
            for (int w = 0; w < P_WARPS; w++) s += red[w][lane];
            s *= (1.f / (float)NODES);
        }
        float sq = s * s;
        #pragma unroll
        for (int ofs = 16; ofs > 0; ofs >>= 1)
            sq += __shfl_xor_sync(0xffffffffu, sq, ofs);
        float v = s * (sq / ((1.f + sq) * sqrtf(sq)));      // v0

        if (mode == 1) {
            float sp = 0.f;
            if (lane < COUT + 1) {
                const float* p = g_ps1 + (size_t)pair * NSLICE * (COUT + 1) + lane;
                #pragma unroll
                for (int sl = 0; sl < NSLICE; sl++) sp += p[sl * (COUT + 1)];
            }
            float zz = __shfl_sync(0xffffffffu, sp, COUT);
            float sj = (lane < COUT) ? sp * (1.f / zz) : 0.f;
            float s2 = sj * sj;
            #pragma unroll
            for (int ofs = 16; ofs > 0; ofs >>= 1)
                s2 += __shfl_xor_sync(0xffffffffu, s2, ofs);
            v = fmaf(sj, s2 / ((1.f + s2) * sqrtf(s2)), v); // + v1
        }
        if (lane < COUT) vsm[lane] = v;
    }
    __syncthreads();

    float vr[8];
    #pragma unroll
    for (int j = 0; j < 8; j++) vr[j] = vsm[par * 8 + j];

    float acc[8];
    #pragma unroll
    for (int j = 0; j < 8; j++) acc[j] = 0.f;
    float z = 0.f;

    #pragma unroll
    for (int k = 0; k < P_ITERS; k++) {
        uint4 n0, n1;
        if (k < P_ITERS - 1) {
            n0 = base[(k + 1) * (2 * P_THREADS) + tid];
            n1 = base[(k + 1) * (2 * P_THREADS) + P_THREADS + tid];
        }

        float u0[8], u1[8];
        {
            unsigned w0[4] = {cur0.x, cur0.y, cur0.z, cur0.w};
            unsigned w1[4] = {cur1.x, cur1.y, cur1.z, cur1.w};
            #pragma unroll
            for (int h = 0; h < 4; h++) {
                float2 f0 = __half22float2(*reinterpret_cast<__half2*>(&w0[h]));
                float2 f1 = __half22float2(*reinterpret_cast<__half2*>(&w1[h]));
                u0[2 * h] = f0.x; u0[2 * h + 1] = f0.y;
                u1[2 * h] = f1.x; u1[2 * h + 1] = f1.y;
            }
        }
        float a0 = 0.f, a1 = 0.f;
        #pragma unroll
        for (int j = 0; j < 8; j++) {
            a0 = fmaf(u0[j], vr[j], a0);
            a1 = fmaf(u1[j], vr[j], a1);
        }
        a0 += __shfl_xor_sync(0xffffffffu, a0, 1);
        a1 += __shfl_xor_sync(0xffffffffu, a1, 1);
        float e0 = fexp(a0);
        float e1 = fexp(a1);
        z += e0 + e1;
        #pragma unroll
        for (int j = 0; j < 8; j++) {
            acc[j] = fmaf(e0, u0[j], acc[j]);
            acc[j] = fmaf(e1, u1[j], acc[j]);
        }
        cur0 = n0;
        cur1 = n1;
    }

    #pragma unroll
    for (int j = 0; j < 8; j++) {
        float v = acc[j];
        #pragma unroll
        for (int ofs = 16; ofs >= 2; ofs >>= 1)
            v += __shfl_xor_sync(0xffffffffu, v, ofs);
        acc[j] = v;
    }
    #pragma unroll
    for (int ofs = 16; ofs >= 2; ofs >>= 1)
        z += __shfl_xor_sync(0xffffffffu, z, ofs);

    __syncthreads();
    if (lane == 0) {
        #pragma unroll
        for (int j = 0; j < 8; j++) red[warp][j] = acc[j];
        red[warp][COUT] = z;
    } else if (lane == 1) {
        #pragma unroll
        for (int j = 0; j < 8; j++) red[warp][8 + j] = acc[j];
    }
    __syncthreads();

    if (tid < COUT + 1) {
        float s = 0.f;
        #pragma unroll
        for (int w = 0; w < P_WARPS; w++) s += red[w][tid];
        float* dst = (mode == 0) ? g_ps1 : g_ps2;
        dst[((size_t)pair * NSLICE + slice) * (COUT + 1) + tid] = s;
    }

    if (mode == 1) {
        __syncthreads();
        if (tid == 0) {
            __threadfence();
            int old = atomicAdd(&g_ctr[pair], 1);
            is_last = (old == NSLICE - 1) ? 1 : 0;
            if (is_last) __threadfence();
        }
        __syncthreads();
        if (is_last && warp == 0) {
            float s = 0.f;
            if (lane < COUT + 1) {
                const float* p =
                    g_ps2 + (size_t)pair * NSLICE * (COUT + 1) + lane;
                #pragma unroll
                for (int sl = 0; sl < NSLICE; sl++) s += p[sl * (COUT + 1)];
            }
            float zz = __shfl_sync(0xffffffffu, s, COUT);
            float sj = (lane < COUT) ? s * (1.f / zz) : 0.f;
            float sq = sj * sj;
            #pragma unroll
            for (int ofs = 16; ofs > 0; ofs >>= 1)
                sq += __shfl_xor_sync(0xffffffffu, sq, ofs);
            float kf = sq / ((1.f + sq) * sqrtf(sq));
            if (lane < COUT) out[pair * COUT + lane] = sj * kf;
            if (lane == 0) g_ctr[pair] = 0;   // self-reset for next replay
        }
    }
}

// ---------------------------------------------------------------------------
extern "C" void kernel_launch(void* const* d_in, const int* in_sizes, int n_in,
                              void* d_out, int out_size) {
    const float* x = (const float*)d_in[0];
    const float* W = (const float*)d_in[1];
    if (in_sizes[0] != BATCH * NODES * CIN) {
        const float* tmp = x; x = W; W = tmp;
    }

    uhat_kernel<<<dim3(NCHUNK, CAPS), K1_THREADS>>>(x, W);
    pass_kernel<<<dim3(NSLICE, PAIRS), P_THREADS>>>(0, nullptr);
    pass_kernel<<<dim3(NSLICE, PAIRS), P_THREADS>>>(1, (float*)d_out);
}